// round 8
// baseline (speedup 1.0000x reference)
#include <cuda_runtime.h>
#include <cuda_bf16.h>
#include <math.h>
#include <stdint.h>

// Problem constants
#define BB   128     // batch
#define TT   1024    // seq
#define DD   128     // in_dim
#define UU   256     // units
#define GG   768     // 3*units (r|u|c)
#define KK3  384     // 3*in_dim (x_t | x_{t-1} | x_{t-2})
#define MTOT (BB * TT)

// ---------------------------------------------------------------------------
// PTX helpers (baseline PTX only — no sm_103a-only features)
// ---------------------------------------------------------------------------
#define CLUSTER_SYNC() do { \
    asm volatile("barrier.cluster.arrive.aligned;" ::: "memory"); \
    asm volatile("barrier.cluster.wait.aligned;" ::: "memory"); \
} while (0)

// remote SMEM store with inline mapa (no live remote-address registers)
__device__ __forceinline__ void dsmem_store_u32(uint32_t saddr, uint32_t rank, uint32_t v) {
    uint32_t remote;
    asm("mapa.shared::cluster.u32 %0, %1, %2;" : "=r"(remote) : "r"(saddr), "r"(rank));
    asm volatile("st.shared::cluster.u32 [%0], %1;" :: "r"(remote), "r"(v) : "memory");
}

// bf16 m16n8k16 MMA (fragment layouts verified in rounds 5-6)
#define MMA_BF16(d, a, b) \
    asm volatile("mma.sync.aligned.m16n8k16.row.col.f32.bf16.bf16.f32 " \
        "{%0,%1,%2,%3}, {%4,%5,%6,%7}, {%8,%9}, {%0,%1,%2,%3};" \
        : "+f"((d)[0]), "+f"((d)[1]), "+f"((d)[2]), "+f"((d)[3]) \
        : "r"((a)[0]), "r"((a)[1]), "r"((a)[2]), "r"((a)[3]), "r"((b)[0]), "r"((b)[1]))

// split (a,b) fp32 pair into packed bf16x2 hi and lo words (low half = a)
__device__ __forceinline__ void split_pack(float a, float b, uint32_t& hi, uint32_t& lo) {
    __nv_bfloat16 ah = __float2bfloat16_rn(a), bh = __float2bfloat16_rn(b);
    __nv_bfloat16 al = __float2bfloat16_rn(a - __bfloat162float(ah));
    __nv_bfloat16 bl = __float2bfloat16_rn(b - __bfloat162float(bh));
    __nv_bfloat162 h2; h2.x = ah; h2.y = bh;
    __nv_bfloat162 l2; l2.x = al; l2.y = bl;
    hi = *reinterpret_cast<uint32_t*>(&h2);
    lo = *reinterpret_cast<uint32_t*>(&l2);
}

// ---------------------------------------------------------------------------
// Scratch (device globals: no allocations allowed)
// ---------------------------------------------------------------------------
__device__ __nv_bfloat16 g_xhi[(size_t)MTOT * DD];     // 32 MB
__device__ __nv_bfloat16 g_xlo[(size_t)MTOT * DD];     // 32 MB
__device__ __nv_bfloat16 g_WThi[GG * KK3];             // combined weights, [col][k3] K-major
__device__ __nv_bfloat16 g_WTlo[GG * KK3];
__device__ float g_Pre[(size_t)BB * TT * GG];          // pre-activations (402 MB)

// ---------------------------------------------------------------------------
// Kernel 1: build combined input weights, K-major, bf16 hi/lo split.
// ---------------------------------------------------------------------------
__global__ void split_w_kernel(const float* __restrict__ iw) {
    int idx = blockIdx.x * blockDim.x + threadIdx.x;
    if (idx >= GG * KK3) return;
    int j  = idx / KK3;
    int k3 = idx - j * KK3;
    int gate = j >> 8;
    int ju   = j & 255;
    int s    = k3 >> 7;
    int k    = k3 & 127;
    const float* row = iw + (size_t)k * (7 * UU);
    float v = 0.f;
    if (gate == 0) {
        float W = row[0 * UU + ju], dW = row[3 * UU + ju], ddW = row[5 * UU + ju];
        v = (s == 0) ? (W + dW + ddW) : (s == 1) ? -(dW + 2.f * ddW) : ddW;
    } else if (gate == 1) {
        float W = row[1 * UU + ju], dW = row[4 * UU + ju], ddW = row[6 * UU + ju];
        v = (s == 0) ? (W + dW + ddW) : (s == 1) ? -(dW + 2.f * ddW) : ddW;
    } else {
        v = (s == 0) ? row[2 * UU + ju] : 0.f;
    }
    __nv_bfloat16 hi = __float2bfloat16_rn(v);
    __nv_bfloat16 lo = __float2bfloat16_rn(v - __bfloat162float(hi));
    g_WThi[idx] = hi;
    g_WTlo[idx] = lo;
}

// ---------------------------------------------------------------------------
// Kernel 2: split x into bf16 hi/lo (4 elems per thread).
// ---------------------------------------------------------------------------
__global__ void split_x_kernel(const float* __restrict__ x) {
    size_t i4 = (size_t)blockIdx.x * blockDim.x + threadIdx.x;
    float4 v = reinterpret_cast<const float4*>(x)[i4];
    __nv_bfloat16 h0 = __float2bfloat16_rn(v.x), h1 = __float2bfloat16_rn(v.y);
    __nv_bfloat16 h2 = __float2bfloat16_rn(v.z), h3 = __float2bfloat16_rn(v.w);
    __nv_bfloat16 l0 = __float2bfloat16_rn(v.x - __bfloat162float(h0));
    __nv_bfloat16 l1 = __float2bfloat16_rn(v.y - __bfloat162float(h1));
    __nv_bfloat16 l2 = __float2bfloat16_rn(v.z - __bfloat162float(h2));
    __nv_bfloat16 l3 = __float2bfloat16_rn(v.w - __bfloat162float(h3));
    __nv_bfloat16 hv[4] = {h0, h1, h2, h3};
    __nv_bfloat16 lv[4] = {l0, l1, l2, l3};
    reinterpret_cast<uint2*>(g_xhi)[i4] = *reinterpret_cast<uint2*>(hv);
    reinterpret_cast<uint2*>(g_xlo)[i4] = *reinterpret_cast<uint2*>(lv);
}

// ---------------------------------------------------------------------------
// Kernel 3: tensor precompute via mma.sync m16n8k16 bf16 (unchanged, proven).
// ---------------------------------------------------------------------------
#define TS 136
#define TILE_FL (128 * TS)
#define MP_SMEM_BYTES (4 * TILE_FL * 2)

__device__ __forceinline__ void ld_tile_A(__nv_bfloat16* dst,
                                          const __nv_bfloat16* __restrict__ src,
                                          int m0, int s, int tid) {
#pragma unroll
    for (int i = 0; i < 8; i++) {
        int idx = tid + i * 256;
        int r   = idx >> 4;
        int c8  = (idx & 15) << 3;
        int m   = m0 + r;
        uint4 val = make_uint4(0u, 0u, 0u, 0u);
        if ((m & (TT - 1)) >= s)
            val = *reinterpret_cast<const uint4*>(src + (size_t)(m - s) * DD + c8);
        *reinterpret_cast<uint4*>(dst + r * TS + c8) = val;
    }
}

__device__ __forceinline__ void ld_tile_B(__nv_bfloat16* dst,
                                          const __nv_bfloat16* __restrict__ src,
                                          int n0, int s, int tid) {
#pragma unroll
    for (int i = 0; i < 8; i++) {
        int idx = tid + i * 256;
        int r   = idx >> 4;
        int c8  = (idx & 15) << 3;
        uint4 val = *reinterpret_cast<const uint4*>(src + (size_t)(n0 + r) * KK3 + s * 128 + c8);
        *reinterpret_cast<uint4*>(dst + r * TS + c8) = val;
    }
}

__global__ void __launch_bounds__(256, 1) mma_pre_kernel(const float* __restrict__ bias) {
    extern __shared__ __nv_bfloat16 sm[];
    __nv_bfloat16* Ahi = sm;
    __nv_bfloat16* Alo = sm + TILE_FL;
    __nv_bfloat16* Bhi = sm + 2 * TILE_FL;
    __nv_bfloat16* Blo = sm + 3 * TILE_FL;

    const int tid  = threadIdx.x;
    const int wid  = tid >> 5;
    const int lane = tid & 31;
    const int wm   = wid & 3;
    const int wn   = wid >> 2;
    const int m0 = blockIdx.x * 128;
    const int n0 = blockIdx.y * 128;
    const int nchunks = (n0 < 512) ? 3 : 1;

    const int qa = (lane & 3) * 2;
    const int gp = lane >> 2;

    float acc[2][8][4];
#pragma unroll
    for (int mf = 0; mf < 2; mf++)
#pragma unroll
        for (int nf = 0; nf < 8; nf++)
#pragma unroll
            for (int q = 0; q < 4; q++) acc[mf][nf][q] = 0.f;

    for (int s = 0; s < nchunks; s++) {
        __syncthreads();
        ld_tile_A(Ahi, g_xhi, m0, s, tid);
        ld_tile_A(Alo, g_xlo, m0, s, tid);
        ld_tile_B(Bhi, g_WThi, n0, s, tid);
        ld_tile_B(Blo, g_WTlo, n0, s, tid);
        __syncthreads();

#pragma unroll
        for (int ks = 0; ks < 8; ks++) {
            const int k0 = ks * 16;
            uint32_t ah[2][4], al[2][4];
#pragma unroll
            for (int mf = 0; mf < 2; mf++) {
                int r = wm * 32 + mf * 16 + gp;
                ah[mf][0] = *reinterpret_cast<const uint32_t*>(&Ahi[r * TS + k0 + qa]);
                ah[mf][1] = *reinterpret_cast<const uint32_t*>(&Ahi[(r + 8) * TS + k0 + qa]);
                ah[mf][2] = *reinterpret_cast<const uint32_t*>(&Ahi[r * TS + k0 + 8 + qa]);
                ah[mf][3] = *reinterpret_cast<const uint32_t*>(&Ahi[(r + 8) * TS + k0 + 8 + qa]);
                al[mf][0] = *reinterpret_cast<const uint32_t*>(&Alo[r * TS + k0 + qa]);
                al[mf][1] = *reinterpret_cast<const uint32_t*>(&Alo[(r + 8) * TS + k0 + qa]);
                al[mf][2] = *reinterpret_cast<const uint32_t*>(&Alo[r * TS + k0 + 8 + qa]);
                al[mf][3] = *reinterpret_cast<const uint32_t*>(&Alo[(r + 8) * TS + k0 + 8 + qa]);
            }
            uint32_t bh[8][2], bl[8][2];
#pragma unroll
            for (int nf = 0; nf < 8; nf++) {
                int n = wn * 64 + nf * 8 + gp;
                bh[nf][0] = *reinterpret_cast<const uint32_t*>(&Bhi[n * TS + k0 + qa]);
                bh[nf][1] = *reinterpret_cast<const uint32_t*>(&Bhi[n * TS + k0 + 8 + qa]);
                bl[nf][0] = *reinterpret_cast<const uint32_t*>(&Blo[n * TS + k0 + qa]);
                bl[nf][1] = *reinterpret_cast<const uint32_t*>(&Blo[n * TS + k0 + 8 + qa]);
            }
#pragma unroll
            for (int mf = 0; mf < 2; mf++)
#pragma unroll
                for (int nf = 0; nf < 8; nf++) {
                    MMA_BF16(acc[mf][nf], ah[mf], bh[nf]);
                    MMA_BF16(acc[mf][nf], ah[mf], bl[nf]);
                    MMA_BF16(acc[mf][nf], al[mf], bh[nf]);
                }
        }
    }

#pragma unroll
    for (int nf = 0; nf < 8; nf++) {
        int col = n0 + wn * 64 + nf * 8 + qa;
        float2 bz = *reinterpret_cast<const float2*>(bias + col);
#pragma unroll
        for (int mf = 0; mf < 2; mf++) {
            int row = m0 + wm * 32 + mf * 16 + gp;
            float2 v0, v1;
            v0.x = acc[mf][nf][0] + bz.x;
            v0.y = acc[mf][nf][1] + bz.y;
            v1.x = acc[mf][nf][2] + bz.x;
            v1.y = acc[mf][nf][3] + bz.y;
            *reinterpret_cast<float2*>(&g_Pre[(size_t)row * GG + col]) = v0;
            *reinterpret_cast<float2*>(&g_Pre[(size_t)(row + 8) * GG + col]) = v1;
        }
    }
}

// ---------------------------------------------------------------------------
// Kernel 4: HMMA recurrence, 8 batch rows / 8-CTA cluster, full-m16 A packing.
//   A rows 0-7  = h_hi (batch rows 0-7)
//   A rows 8-15 = h_lo (batch rows 0-7)
//   => c[0]+c[2] (and c[1]+c[3]) is the exact hi+lo combine, no shuffle.
// 16 clusters x 8 CTAs = 128 CTAs; CTA rank cr owns cols [cr*32,(cr+1)*32)
// of each gate. Phase 1: 16 warps = 8 col-strips x 2 K-halves (chain 8).
// Phase 2: 16 warps = 4 col-strips x 4 K-quarters (chain 4).
// Weight regs: 8*4 + 4*4 = 48 packed words (vs 96 in round 6).
// A-pair SMEM stride 24 words / padded fp32 arrays: conflict-free.
// ---------------------------------------------------------------------------
__global__ void __launch_bounds__(512, 1) __cluster_dims__(8, 1, 1)
rnn_kernel(const float* __restrict__ Wh, float* __restrict__ out) {
    __shared__ uint32_t hAp[128 * 24];   // [pair p][row16 r] stride 24
    __shared__ uint32_t rhAp[128 * 24];
    __shared__ float h8f[32 * 9];        // [own unit lu][row8], stride 9
    __shared__ float uS[32 * 9];         // update gate, same layout
    __shared__ float red1[2 * 8 * 72];   // [kh][row8][col64], stride 72
    __shared__ float red2[4 * 8 * 40];   // [kq][row8][col32], stride 40

    const int tid  = threadIdx.x;
    const int w    = tid >> 5;
    const int lane = tid & 31;
    const int gp   = lane >> 2;
    const int tg   = lane & 3;
    const int qa   = tg * 2;
    uint32_t cr;
    asm("mov.u32 %0, %%cluster_ctarank;" : "=r"(cr));
    const int b0 = (blockIdx.x >> 3) * 8;   // cluster id * 8 batch rows

    // ---- warp roles ----
    const int ns1 = w & 7;   // phase1 col strip (0-3: r, 4-7: u)
    const int kh1 = w >> 3;  // phase1 K-half
    const int ns2 = w & 3;   // phase2 col strip (cand)
    const int kq2 = w >> 2;  // phase2 K-quarter

    // ---- one-time: weight fragments (packed bf16 hi/lo) ----
    uint32_t b1h[8][2], b1l[8][2];
    {
        int gcol = (ns1 < 4) ? ((int)cr * 32 + ns1 * 8 + gp)
                             : (256 + (int)cr * 32 + (ns1 - 4) * 8 + gp);
#pragma unroll
        for (int ch = 0; ch < 8; ch++) {
            int k0 = kh1 * 128 + ch * 16;
            float v00 = Wh[(size_t)(k0 + qa) * GG + gcol];
            float v01 = Wh[(size_t)(k0 + qa + 1) * GG + gcol];
            float v10 = Wh[(size_t)(k0 + 8 + qa) * GG + gcol];
            float v11 = Wh[(size_t)(k0 + 8 + qa + 1) * GG + gcol];
            split_pack(v00, v01, b1h[ch][0], b1l[ch][0]);
            split_pack(v10, v11, b1h[ch][1], b1l[ch][1]);
        }
    }
    uint32_t b2h[4][2], b2l[4][2];
    {
        int gcol = 512 + (int)cr * 32 + ns2 * 8 + gp;
#pragma unroll
        for (int ch = 0; ch < 4; ch++) {
            int k0 = kq2 * 64 + ch * 16;
            float v00 = Wh[(size_t)(k0 + qa) * GG + gcol];
            float v01 = Wh[(size_t)(k0 + qa + 1) * GG + gcol];
            float v10 = Wh[(size_t)(k0 + 8 + qa) * GG + gcol];
            float v11 = Wh[(size_t)(k0 + 8 + qa + 1) * GG + gcol];
            split_pack(v00, v01, b2h[ch][0], b2l[ch][0]);
            split_pack(v10, v11, b2h[ch][1], b2l[ch][1]);
        }
    }

    // ---- init state ----
    for (int i = tid; i < 128 * 24; i += 512) { hAp[i] = 0u; rhAp[i] = 0u; }
    for (int i = tid; i < 32 * 9; i += 512)  h8f[i] = 0.f;
    const uint32_t rh_base = (uint32_t)__cvta_generic_to_shared(rhAp);
    const uint32_t hA_base = (uint32_t)__cvta_generic_to_shared(hAp);
    __syncthreads();
    CLUSTER_SYNC();

    // finalize identities
    const int row1 = tid >> 6;          // finalize-1: row 0..7
    const int col1 = tid & 63;          // finalize-1: col 0..63 (r: 0-31, u: 32-63)
    const int gcol1f = (col1 < 32) ? ((int)cr * 32 + col1)
                                   : (256 + (int)cr * 32 + (col1 - 32));
    const float* p1ptr = g_Pre + (size_t)(b0 + row1) * TT * GG + gcol1f;

    const int row2 = tid >> 5;          // finalize-2 (tid<256): row 0..7
    const int lu2  = tid & 31;          // finalize-2: own unit 0..31
    const float* p2ptr = g_Pre + (size_t)(b0 + row2) * TT * GG + 512 + cr * 32 + lu2;
    float* outp = out + (size_t)(b0 + row2) * TT * UU + cr * 32 + lu2;

    for (int t = 0; t < TT; t++) {
        float p1 = p1ptr[(size_t)t * GG];
        float p2 = 0.f;
        if (tid < 256) p2 = p2ptr[(size_t)t * GG];

        // ---- phase 1: h @ [Whr|Whu] strip over K-half (chain 8, full m16) ----
        float c1h[4] = {0.f, 0.f, 0.f, 0.f};
        float c1l[4] = {0.f, 0.f, 0.f, 0.f};
#pragma unroll
        for (int ch = 0; ch < 8; ch++) {
            int p0 = kh1 * 64 + ch * 8;
            uint32_t a[4];
            a[0] = hAp[(p0 + tg) * 24 + gp];
            a[1] = hAp[(p0 + tg) * 24 + gp + 8];
            a[2] = hAp[(p0 + 4 + tg) * 24 + gp];
            a[3] = hAp[(p0 + 4 + tg) * 24 + gp + 8];
            MMA_BF16(c1h, a, b1h[ch]);
            MMA_BF16(c1l, a, b1l[ch]);
        }
        {
            float v0 = c1h[0] + c1l[0] + c1h[2] + c1l[2];
            float v1 = c1h[1] + c1l[1] + c1h[3] + c1l[3];
            *reinterpret_cast<float2*>(&red1[kh1 * 576 + gp * 72 + ns1 * 8 + qa]) =
                make_float2(v0, v1);
        }
        __syncthreads();

        // ---- finalize 1: r,u gates (512 items, 1/thread) ----
        {
            float v = red1[row1 * 72 + col1] + red1[576 + row1 * 72 + col1] + p1;
            float sg = 1.f / (1.f + __expf(-v));
            if (col1 < 32) {   // r-gate: rh slice -> broadcast to all 8 CTAs
                float rh = sg * h8f[col1 * 9 + row1];
                float rh1 = __shfl_down_sync(0xffffffffu, rh, 1);
                if (!(col1 & 1)) {
                    uint32_t whi, wlo;
                    split_pack(rh, rh1, whi, wlo);
                    int p = (int)cr * 16 + (col1 >> 1);
                    uint32_t offh = rh_base + (uint32_t)((p * 24 + row1) * 4);
                    uint32_t offl = rh_base + (uint32_t)((p * 24 + row1 + 8) * 4);
#pragma unroll
                    for (int rr = 0; rr < 8; rr++) {
                        dsmem_store_u32(offh, (uint32_t)rr, whi);
                        dsmem_store_u32(offl, (uint32_t)rr, wlo);
                    }
                }
            } else {           // u-gate: local
                uS[(col1 - 32) * 9 + row1] = sg;
            }
        }
        CLUSTER_SYNC();   // all rh slices visible cluster-wide

        // ---- phase 2: (r*h) @ Whh strip over K-quarter (chain 4) ----
        float d2h[4] = {0.f, 0.f, 0.f, 0.f};
        float d2l[4] = {0.f, 0.f, 0.f, 0.f};
#pragma unroll
        for (int ch = 0; ch < 4; ch++) {
            int p0 = kq2 * 32 + ch * 8;
            uint32_t a[4];
            a[0] = rhAp[(p0 + tg) * 24 + gp];
            a[1] = rhAp[(p0 + tg) * 24 + gp + 8];
            a[2] = rhAp[(p0 + 4 + tg) * 24 + gp];
            a[3] = rhAp[(p0 + 4 + tg) * 24 + gp + 8];
            MMA_BF16(d2h, a, b2h[ch]);
            MMA_BF16(d2l, a, b2l[ch]);
        }
        {
            float v0 = d2h[0] + d2l[0] + d2h[2] + d2l[2];
            float v1 = d2h[1] + d2l[1] + d2h[3] + d2l[3];
            *reinterpret_cast<float2*>(&red2[kq2 * 320 + gp * 40 + ns2 * 8 + qa]) =
                make_float2(v0, v1);
        }
        __syncthreads();

        // ---- finalize 2: cand + state update + output + h exchange ----
        if (tid < 256) {
            float v = red2[row2 * 40 + lu2] + red2[320 + row2 * 40 + lu2] +
                      red2[640 + row2 * 40 + lu2] + red2[960 + row2 * 40 + lu2] + p2;
            float av = fabsf(v), e = __expf(-2.f * av);
            float cand = copysignf((1.f - e) / (1.f + e), v);
            float u = uS[lu2 * 9 + row2];
            float hold = h8f[lu2 * 9 + row2];
            float hn = u * hold + (1.f - u) * cand;
            outp[(size_t)t * UU] = hn;
            h8f[lu2 * 9 + row2] = hn;
            float hn1 = __shfl_down_sync(0xffffffffu, hn, 1);
            if (!(lu2 & 1)) {
                uint32_t whi, wlo;
                split_pack(hn, hn1, whi, wlo);
                int p = (int)cr * 16 + (lu2 >> 1);
                uint32_t offh = hA_base + (uint32_t)((p * 24 + row2) * 4);
                uint32_t offl = hA_base + (uint32_t)((p * 24 + row2 + 8) * 4);
#pragma unroll
                for (int rr = 0; rr < 8; rr++) {
                    dsmem_store_u32(offh, (uint32_t)rr, whi);
                    dsmem_store_u32(offl, (uint32_t)rr, wlo);
                }
            }
        }
        CLUSTER_SYNC();   // h_new visible cluster-wide
    }
}

// ---------------------------------------------------------------------------
// Launch
// ---------------------------------------------------------------------------
extern "C" void kernel_launch(void* const* d_in, const int* in_sizes, int n_in,
                              void* d_out, int out_size) {
    const float* x    = (const float*)d_in[0];
    const float* iw   = (const float*)d_in[1];
    const float* hw   = (const float*)d_in[2];
    const float* bias = (const float*)d_in[3];
    float* out = (float*)d_out;

    static int attr_set = 0;
    if (!attr_set) {
        cudaFuncSetAttribute(mma_pre_kernel, cudaFuncAttributeMaxDynamicSharedMemorySize,
                             MP_SMEM_BYTES);
        attr_set = 1;
    }

    split_w_kernel<<<(GG * KK3 + 255) / 256, 256>>>(iw);
    split_x_kernel<<<(MTOT * DD / 4) / 256, 256>>>(x);

    dim3 pgrid(MTOT / 128, GG / 128);   // 1024 x 6
    mma_pre_kernel<<<pgrid, 256, MP_SMEM_BYTES>>>(bias);

    // 128 CTAs = 16 clusters of 8 (8 batch rows per cluster)
    rnn_kernel<<<BB, 512>>>(hw, out);
}

// round 9
// speedup vs baseline: 4.6658x; 4.6658x over previous
#include <cuda_runtime.h>
#include <cuda_bf16.h>
#include <math.h>
#include <stdint.h>

// Problem constants
#define BB   128     // batch
#define TT   1024    // seq
#define DD   128     // in_dim
#define UU   256     // units
#define GG   768     // 3*units (r|u|c)
#define KK3  384     // 3*in_dim (x_t | x_{t-1} | x_{t-2})
#define MTOT (BB * TT)

// ---------------------------------------------------------------------------
// PTX helpers (baseline PTX only — no sm_103a-only features)
// ---------------------------------------------------------------------------
#define CLUSTER_SYNC() do { \
    asm volatile("barrier.cluster.arrive.aligned;" ::: "memory"); \
    asm volatile("barrier.cluster.wait.aligned;" ::: "memory"); \
} while (0)

// remote SMEM store with inline mapa (no live remote-address registers)
__device__ __forceinline__ void dsmem_store_u32(uint32_t saddr, uint32_t rank, uint32_t v) {
    uint32_t remote;
    asm("mapa.shared::cluster.u32 %0, %1, %2;" : "=r"(remote) : "r"(saddr), "r"(rank));
    asm volatile("st.shared::cluster.u32 [%0], %1;" :: "r"(remote), "r"(v) : "memory");
}

// cp.async (sm_80+ baseline): zero-register-latency prefetch into SMEM
__device__ __forceinline__ void cp_async8(uint32_t smem, const void* g) {
    asm volatile("cp.async.ca.shared.global [%0], [%1], 8;" :: "r"(smem), "l"(g) : "memory");
}
__device__ __forceinline__ void cp_async4(uint32_t smem, const void* g) {
    asm volatile("cp.async.ca.shared.global [%0], [%1], 4;" :: "r"(smem), "l"(g) : "memory");
}
#define CP_COMMIT() asm volatile("cp.async.commit_group;" ::: "memory")
#define CP_WAIT1()  asm volatile("cp.async.wait_group 1;" ::: "memory")

// bf16 m16n8k16 MMA (fragment layouts verified in rounds 5-6)
#define MMA_BF16(d, a, b) \
    asm volatile("mma.sync.aligned.m16n8k16.row.col.f32.bf16.bf16.f32 " \
        "{%0,%1,%2,%3}, {%4,%5,%6,%7}, {%8,%9}, {%0,%1,%2,%3};" \
        : "+f"((d)[0]), "+f"((d)[1]), "+f"((d)[2]), "+f"((d)[3]) \
        : "r"((a)[0]), "r"((a)[1]), "r"((a)[2]), "r"((a)[3]), "r"((b)[0]), "r"((b)[1]))

// split (a,b) fp32 pair into packed bf16x2 hi and lo words (low half = a)
__device__ __forceinline__ void split_pack(float a, float b, uint32_t& hi, uint32_t& lo) {
    __nv_bfloat16 ah = __float2bfloat16_rn(a), bh = __float2bfloat16_rn(b);
    __nv_bfloat16 al = __float2bfloat16_rn(a - __bfloat162float(ah));
    __nv_bfloat16 bl = __float2bfloat16_rn(b - __bfloat162float(bh));
    __nv_bfloat162 h2; h2.x = ah; h2.y = bh;
    __nv_bfloat162 l2; l2.x = al; l2.y = bl;
    hi = *reinterpret_cast<uint32_t*>(&h2);
    lo = *reinterpret_cast<uint32_t*>(&l2);
}

// ---------------------------------------------------------------------------
// Scratch (device globals: no allocations allowed)
// ---------------------------------------------------------------------------
__device__ __nv_bfloat16 g_xhi[(size_t)MTOT * DD];     // 32 MB
__device__ __nv_bfloat16 g_xlo[(size_t)MTOT * DD];     // 32 MB
__device__ __nv_bfloat16 g_WThi[GG * KK3];             // combined weights, [col][k3] K-major
__device__ __nv_bfloat16 g_WTlo[GG * KK3];
__device__ float g_Pre[(size_t)BB * TT * GG];          // pre-activations (402 MB)

// ---------------------------------------------------------------------------
// Kernel 1: build combined input weights, K-major, bf16 hi/lo split.
// ---------------------------------------------------------------------------
__global__ void split_w_kernel(const float* __restrict__ iw) {
    int idx = blockIdx.x * blockDim.x + threadIdx.x;
    if (idx >= GG * KK3) return;
    int j  = idx / KK3;
    int k3 = idx - j * KK3;
    int gate = j >> 8;
    int ju   = j & 255;
    int s    = k3 >> 7;
    int k    = k3 & 127;
    const float* row = iw + (size_t)k * (7 * UU);
    float v = 0.f;
    if (gate == 0) {
        float W = row[0 * UU + ju], dW = row[3 * UU + ju], ddW = row[5 * UU + ju];
        v = (s == 0) ? (W + dW + ddW) : (s == 1) ? -(dW + 2.f * ddW) : ddW;
    } else if (gate == 1) {
        float W = row[1 * UU + ju], dW = row[4 * UU + ju], ddW = row[6 * UU + ju];
        v = (s == 0) ? (W + dW + ddW) : (s == 1) ? -(dW + 2.f * ddW) : ddW;
    } else {
        v = (s == 0) ? row[2 * UU + ju] : 0.f;
    }
    __nv_bfloat16 hi = __float2bfloat16_rn(v);
    __nv_bfloat16 lo = __float2bfloat16_rn(v - __bfloat162float(hi));
    g_WThi[idx] = hi;
    g_WTlo[idx] = lo;
}

// ---------------------------------------------------------------------------
// Kernel 2: split x into bf16 hi/lo (4 elems per thread).
// ---------------------------------------------------------------------------
__global__ void split_x_kernel(const float* __restrict__ x) {
    size_t i4 = (size_t)blockIdx.x * blockDim.x + threadIdx.x;
    float4 v = reinterpret_cast<const float4*>(x)[i4];
    __nv_bfloat16 h0 = __float2bfloat16_rn(v.x), h1 = __float2bfloat16_rn(v.y);
    __nv_bfloat16 h2 = __float2bfloat16_rn(v.z), h3 = __float2bfloat16_rn(v.w);
    __nv_bfloat16 l0 = __float2bfloat16_rn(v.x - __bfloat162float(h0));
    __nv_bfloat16 l1 = __float2bfloat16_rn(v.y - __bfloat162float(h1));
    __nv_bfloat16 l2 = __float2bfloat16_rn(v.z - __bfloat162float(h2));
    __nv_bfloat16 l3 = __float2bfloat16_rn(v.w - __bfloat162float(h3));
    __nv_bfloat16 hv[4] = {h0, h1, h2, h3};
    __nv_bfloat16 lv[4] = {l0, l1, l2, l3};
    reinterpret_cast<uint2*>(g_xhi)[i4] = *reinterpret_cast<uint2*>(hv);
    reinterpret_cast<uint2*>(g_xlo)[i4] = *reinterpret_cast<uint2*>(lv);
}

// ---------------------------------------------------------------------------
// Kernel 3: tensor precompute via mma.sync m16n8k16 bf16 (unchanged, proven).
// ---------------------------------------------------------------------------
#define TS 136
#define TILE_FL (128 * TS)
#define MP_SMEM_BYTES (4 * TILE_FL * 2)

__device__ __forceinline__ void ld_tile_A(__nv_bfloat16* dst,
                                          const __nv_bfloat16* __restrict__ src,
                                          int m0, int s, int tid) {
#pragma unroll
    for (int i = 0; i < 8; i++) {
        int idx = tid + i * 256;
        int r   = idx >> 4;
        int c8  = (idx & 15) << 3;
        int m   = m0 + r;
        uint4 val = make_uint4(0u, 0u, 0u, 0u);
        if ((m & (TT - 1)) >= s)
            val = *reinterpret_cast<const uint4*>(src + (size_t)(m - s) * DD + c8);
        *reinterpret_cast<uint4*>(dst + r * TS + c8) = val;
    }
}

__device__ __forceinline__ void ld_tile_B(__nv_bfloat16* dst,
                                          const __nv_bfloat16* __restrict__ src,
                                          int n0, int s, int tid) {
#pragma unroll
    for (int i = 0; i < 8; i++) {
        int idx = tid + i * 256;
        int r   = idx >> 4;
        int c8  = (idx & 15) << 3;
        uint4 val = *reinterpret_cast<const uint4*>(src + (size_t)(n0 + r) * KK3 + s * 128 + c8);
        *reinterpret_cast<uint4*>(dst + r * TS + c8) = val;
    }
}

__global__ void __launch_bounds__(256, 1) mma_pre_kernel(const float* __restrict__ bias) {
    extern __shared__ __nv_bfloat16 sm[];
    __nv_bfloat16* Ahi = sm;
    __nv_bfloat16* Alo = sm + TILE_FL;
    __nv_bfloat16* Bhi = sm + 2 * TILE_FL;
    __nv_bfloat16* Blo = sm + 3 * TILE_FL;

    const int tid  = threadIdx.x;
    const int wid  = tid >> 5;
    const int lane = tid & 31;
    const int wm   = wid & 3;
    const int wn   = wid >> 2;
    const int m0 = blockIdx.x * 128;
    const int n0 = blockIdx.y * 128;
    const int nchunks = (n0 < 512) ? 3 : 1;

    const int qa = (lane & 3) * 2;
    const int gp = lane >> 2;

    float acc[2][8][4];
#pragma unroll
    for (int mf = 0; mf < 2; mf++)
#pragma unroll
        for (int nf = 0; nf < 8; nf++)
#pragma unroll
            for (int q = 0; q < 4; q++) acc[mf][nf][q] = 0.f;

    for (int s = 0; s < nchunks; s++) {
        __syncthreads();
        ld_tile_A(Ahi, g_xhi, m0, s, tid);
        ld_tile_A(Alo, g_xlo, m0, s, tid);
        ld_tile_B(Bhi, g_WThi, n0, s, tid);
        ld_tile_B(Blo, g_WTlo, n0, s, tid);
        __syncthreads();

#pragma unroll
        for (int ks = 0; ks < 8; ks++) {
            const int k0 = ks * 16;
            uint32_t ah[2][4], al[2][4];
#pragma unroll
            for (int mf = 0; mf < 2; mf++) {
                int r = wm * 32 + mf * 16 + gp;
                ah[mf][0] = *reinterpret_cast<const uint32_t*>(&Ahi[r * TS + k0 + qa]);
                ah[mf][1] = *reinterpret_cast<const uint32_t*>(&Ahi[(r + 8) * TS + k0 + qa]);
                ah[mf][2] = *reinterpret_cast<const uint32_t*>(&Ahi[r * TS + k0 + 8 + qa]);
                ah[mf][3] = *reinterpret_cast<const uint32_t*>(&Ahi[(r + 8) * TS + k0 + 8 + qa]);
                al[mf][0] = *reinterpret_cast<const uint32_t*>(&Alo[r * TS + k0 + qa]);
                al[mf][1] = *reinterpret_cast<const uint32_t*>(&Alo[(r + 8) * TS + k0 + qa]);
                al[mf][2] = *reinterpret_cast<const uint32_t*>(&Alo[r * TS + k0 + 8 + qa]);
                al[mf][3] = *reinterpret_cast<const uint32_t*>(&Alo[(r + 8) * TS + k0 + 8 + qa]);
            }
            uint32_t bh[8][2], bl[8][2];
#pragma unroll
            for (int nf = 0; nf < 8; nf++) {
                int n = wn * 64 + nf * 8 + gp;
                bh[nf][0] = *reinterpret_cast<const uint32_t*>(&Bhi[n * TS + k0 + qa]);
                bh[nf][1] = *reinterpret_cast<const uint32_t*>(&Bhi[n * TS + k0 + 8 + qa]);
                bl[nf][0] = *reinterpret_cast<const uint32_t*>(&Blo[n * TS + k0 + qa]);
                bl[nf][1] = *reinterpret_cast<const uint32_t*>(&Blo[n * TS + k0 + 8 + qa]);
            }
#pragma unroll
            for (int mf = 0; mf < 2; mf++)
#pragma unroll
                for (int nf = 0; nf < 8; nf++) {
                    MMA_BF16(acc[mf][nf], ah[mf], bh[nf]);
                    MMA_BF16(acc[mf][nf], ah[mf], bl[nf]);
                    MMA_BF16(acc[mf][nf], al[mf], bh[nf]);
                }
        }
    }

#pragma unroll
    for (int nf = 0; nf < 8; nf++) {
        int col = n0 + wn * 64 + nf * 8 + qa;
        float2 bz = *reinterpret_cast<const float2*>(bias + col);
#pragma unroll
        for (int mf = 0; mf < 2; mf++) {
            int row = m0 + wm * 32 + mf * 16 + gp;
            float2 v0, v1;
            v0.x = acc[mf][nf][0] + bz.x;
            v0.y = acc[mf][nf][1] + bz.y;
            v1.x = acc[mf][nf][2] + bz.x;
            v1.y = acc[mf][nf][3] + bz.y;
            *reinterpret_cast<float2*>(&g_Pre[(size_t)row * GG + col]) = v0;
            *reinterpret_cast<float2*>(&g_Pre[(size_t)(row + 8) * GG + col]) = v1;
        }
    }
}

// ---------------------------------------------------------------------------
// Kernel 4: HMMA recurrence — ROUND-6 structure (4-CTA cluster, 4 rows,
// proven 4355us) + round-9 deltas:
//   (a) cp.async SMEM double-buffered prefetch of p1/p2 (zero reg cost)
//   (b) phase-1 hi/lo accumulator chains split (chain 32 -> 16, +4 regs)
//   (c) inline mapa at store sites (-8 regs)  => net -4 regs vs round 6
// ---------------------------------------------------------------------------
__global__ void __launch_bounds__(512, 1) __cluster_dims__(4, 1, 1)
rnn_kernel(const float* __restrict__ Wh, float* __restrict__ out) {
    __shared__ uint32_t hAp[1024];    // [128 pairs][8 rows] rows 0-3 hi, 4-7 lo
    __shared__ uint32_t rhAp[1024];
    __shared__ float h4f[1024];       // [unit][row] fp32 hidden state
    __shared__ float uS[256];         // [row][col] update gate slice
    __shared__ float red[512];        // [kh][row][col] phase2 reduction
    __shared__ float2 p1buf[2][256];  // prefetched phase-1 pre-activations
    __shared__ float  p2buf[2][256];  // prefetched cand pre-activations

    const int tid  = threadIdx.x;
    const int w    = tid >> 5;
    const int lane = tid & 31;
    const int gp   = lane >> 2;
    const int tg   = lane & 3;
    const int qa   = tg * 2;
    uint32_t cr;
    asm("mov.u32 %0, %%cluster_ctarank;" : "=r"(cr));
    const int b0 = (blockIdx.x >> 2) * 4;

    // ---- one-time: load weight fragments into registers (bf16 hi/lo) ----
    uint32_t b1h[16][2], b1l[16][2];
    {
        int gcol = (w < 8) ? ((int)cr * 64 + w * 8 + gp)
                           : (256 + (int)cr * 64 + (w - 8) * 8 + gp);
#pragma unroll
        for (int ch = 0; ch < 16; ch++) {
            int k0 = ch * 16;
            float v00 = Wh[(size_t)(k0 + qa) * GG + gcol];
            float v01 = Wh[(size_t)(k0 + qa + 1) * GG + gcol];
            float v10 = Wh[(size_t)(k0 + 8 + qa) * GG + gcol];
            float v11 = Wh[(size_t)(k0 + 8 + qa + 1) * GG + gcol];
            split_pack(v00, v01, b1h[ch][0], b1l[ch][0]);
            split_pack(v10, v11, b1h[ch][1], b1l[ch][1]);
        }
    }
    const int ns = w & 7, kh = w >> 3;
    uint32_t b2h[8][2], b2l[8][2];
    {
        int gcol = 512 + (int)cr * 64 + ns * 8 + gp;
#pragma unroll
        for (int ch = 0; ch < 8; ch++) {
            int k0 = kh * 128 + ch * 16;
            float v00 = Wh[(size_t)(k0 + qa) * GG + gcol];
            float v01 = Wh[(size_t)(k0 + qa + 1) * GG + gcol];
            float v10 = Wh[(size_t)(k0 + 8 + qa) * GG + gcol];
            float v11 = Wh[(size_t)(k0 + 8 + qa + 1) * GG + gcol];
            split_pack(v00, v01, b2h[ch][0], b2l[ch][0]);
            split_pack(v10, v11, b2h[ch][1], b2l[ch][1]);
        }
    }

    // ---- init state ----
    for (int i = tid; i < 1024; i += 512) { hAp[i] = 0u; h4f[i] = 0.f; }
    const uint32_t rh_base = (uint32_t)__cvta_generic_to_shared(rhAp);
    const uint32_t hA_base = (uint32_t)__cvta_generic_to_shared(hAp);
    __syncthreads();
    CLUSTER_SYNC();

    // finalize-2 identities
    const int r2 = (tid >> 6) & 3;
    const int c2 = tid & 63;
    const float* p2ptr = g_Pre + (size_t)(b0 + r2) * TT * GG + 512 + cr * 64 + c2;
    float* outp = out + ((size_t)(b0 + r2) * TT) * UU + cr * 64 + c2;

    // phase-1 p1 pointer (lanes 0-15, i.e. gp<4, use it)
    const int colbase1 = (w < 8) ? ((int)cr * 64 + w * 8 + qa)
                                 : (256 + (int)cr * 64 + (w - 8) * 8 + qa);
    const float* p1ptr = g_Pre + (size_t)(b0 + (gp & 3)) * TT * GG + colbase1;

    // cp.async slot addresses (issuer == reader for every slot)
    const uint32_t p1slot = (uint32_t)__cvta_generic_to_shared(&p1buf[0][w * 16 + lane]);
    const uint32_t p2slot = (uint32_t)__cvta_generic_to_shared(&p2buf[0][tid]);

    // prologue: prefetch step 0
    if (lane < 16) cp_async8(p1slot, p1ptr);
    if (tid < 256) cp_async4(p2slot, p2ptr);
    CP_COMMIT();

    for (int t = 0; t < TT; t++) {
        const int tn = (t + 1) & (TT - 1);   // wrap keeps prefetch in-bounds
        const int bc = t & 1, bn = bc ^ 1;

        // issue prefetch for t+1 (completes during this step's compute)
        if (lane < 16) cp_async8(p1slot + (uint32_t)bn * 2048u, p1ptr + (size_t)tn * GG);
        if (tid < 256) cp_async4(p2slot + (uint32_t)bn * 1024u, p2ptr + (size_t)tn * GG);
        CP_COMMIT();

        // ---- phase 1: h @ [Whr|Whu] strip, split hi/lo chains (16 deep) ----
        float chA[4] = {0.f, 0.f, 0.f, 0.f};
        float clA[4] = {0.f, 0.f, 0.f, 0.f};
#pragma unroll
        for (int ch = 0; ch < 16; ch++) {
            uint32_t a[4];
            a[0] = hAp[(ch * 8 + tg) * 8 + gp];
            a[2] = hAp[(ch * 8 + tg + 4) * 8 + gp];
            a[1] = 0u; a[3] = 0u;
            MMA_BF16(chA, a, b1h[ch]);
            MMA_BF16(clA, a, b1l[ch]);
        }
        CP_WAIT1();   // step-t prefetch group complete (t+1 may stay in flight)
        float v0 = chA[0] + clA[0];
        float v1 = chA[1] + clA[1];
        v0 += __shfl_down_sync(0xffffffffu, v0, 16);
        v1 += __shfl_down_sync(0xffffffffu, v1, 16);
        if (gp < 4) {
            float2 p1 = p1buf[bc][w * 16 + lane];
            v0 += p1.x; v1 += p1.y;
            float sg0 = 1.f / (1.f + __expf(-v0));
            float sg1 = 1.f / (1.f + __expf(-v1));
            if (w < 8) {   // r-gate: produce rh slice, broadcast to cluster
                int u0 = (int)cr * 64 + w * 8 + qa;
                float rh0 = sg0 * h4f[u0 * 4 + gp];
                float rh1 = sg1 * h4f[(u0 + 1) * 4 + gp];
                uint32_t whi, wlo;
                split_pack(rh0, rh1, whi, wlo);
                uint32_t offh = rh_base + (uint32_t)(((u0 >> 1) * 8 + gp) * 4);
                uint32_t offl = rh_base + (uint32_t)(((u0 >> 1) * 8 + gp + 4) * 4);
#pragma unroll
                for (int rr = 0; rr < 4; rr++) {
                    dsmem_store_u32(offh, (uint32_t)rr, whi);
                    dsmem_store_u32(offl, (uint32_t)rr, wlo);
                }
            } else {       // u-gate: local
                *reinterpret_cast<float2*>(&uS[gp * 64 + (w - 8) * 8 + qa]) =
                    make_float2(sg0, sg1);
            }
        }
        CLUSTER_SYNC();   // rh slices visible cluster-wide

        // ---- phase 2: (r*h) @ Whh strip over K-half (fused chain, as R6) ----
        float d[4] = {0.f, 0.f, 0.f, 0.f};
#pragma unroll
        for (int ch = 0; ch < 8; ch++) {
            uint32_t a[4];
            a[0] = rhAp[(kh * 64 + ch * 8 + tg) * 8 + gp];
            a[2] = rhAp[(kh * 64 + ch * 8 + tg + 4) * 8 + gp];
            a[1] = 0u; a[3] = 0u;
            MMA_BF16(d, a, b2h[ch]);
            MMA_BF16(d, a, b2l[ch]);
        }
        float y0 = d[0] + __shfl_down_sync(0xffffffffu, d[0], 16);
        float y1 = d[1] + __shfl_down_sync(0xffffffffu, d[1], 16);
        if (gp < 4)
            *reinterpret_cast<float2*>(&red[kh * 256 + gp * 64 + ns * 8 + qa]) =
                make_float2(y0, y1);
        __syncthreads();

        // ---- finalize: cand + state update + output + h exchange ----
        if (tid < 256) {
            float v = red[r2 * 64 + c2] + red[256 + r2 * 64 + c2] + p2buf[bc][tid];
            float av = fabsf(v), e = __expf(-2.f * av);
            float cand = copysignf((1.f - e) / (1.f + e), v);
            float u = uS[r2 * 64 + c2];
            int unit = (int)cr * 64 + c2;
            float hold = h4f[unit * 4 + r2];
            float hn = u * hold + (1.f - u) * cand;
            outp[(size_t)t * UU] = hn;
            h4f[unit * 4 + r2] = hn;
            float hn1 = __shfl_down_sync(0xffffffffu, hn, 1);
            if (!(c2 & 1)) {
                uint32_t whi, wlo;
                split_pack(hn, hn1, whi, wlo);
                uint32_t offh = hA_base + (uint32_t)(((unit >> 1) * 8 + r2) * 4);
                uint32_t offl = hA_base + (uint32_t)(((unit >> 1) * 8 + r2 + 4) * 4);
#pragma unroll
                for (int rr = 0; rr < 4; rr++) {
                    dsmem_store_u32(offh, (uint32_t)rr, whi);
                    dsmem_store_u32(offl, (uint32_t)rr, wlo);
                }
            }
        }
        CLUSTER_SYNC();   // h_new visible cluster-wide
    }
}

// ---------------------------------------------------------------------------
// Launch
// ---------------------------------------------------------------------------
extern "C" void kernel_launch(void* const* d_in, const int* in_sizes, int n_in,
                              void* d_out, int out_size) {
    const float* x    = (const float*)d_in[0];
    const float* iw   = (const float*)d_in[1];
    const float* hw   = (const float*)d_in[2];
    const float* bias = (const float*)d_in[3];
    float* out = (float*)d_out;

    static int attr_set = 0;
    if (!attr_set) {
        cudaFuncSetAttribute(mma_pre_kernel, cudaFuncAttributeMaxDynamicSharedMemorySize,
                             MP_SMEM_BYTES);
        attr_set = 1;
    }

    split_w_kernel<<<(GG * KK3 + 255) / 256, 256>>>(iw);
    split_x_kernel<<<(MTOT * DD / 4) / 256, 256>>>(x);

    dim3 pgrid(MTOT / 128, GG / 128);   // 1024 x 6
    mma_pre_kernel<<<pgrid, 256, MP_SMEM_BYTES>>>(bias);

    // 128 CTAs = 32 clusters of 4 (4 batch rows per cluster)
    rnn_kernel<<<BB, 512>>>(hw, out);
}